// round 6
// baseline (speedup 1.0000x reference)
#include <cuda_runtime.h>
#include <cuda_bf16.h>
#include <cstdint>

#define Hn    250       // hidden units
#define Bn    256       // batch
#define Tn    512       // time steps
#define Gn    1000      // 4*H gate rows
#define HP    256       // padded hidden stride (elements / u64 pairs)
#define KP    252       // padded K for recurrent GEMM
#define KCn   63        // KP/4 chunks

// ---------------- scratch (device globals; zero-initialized at load) ----------------
__device__ float              g_xg[(size_t)Tn * Bn * Gn];          // input-gate contributions
__device__ float              g_h1[(size_t)(Tn + 1) * Bn * HP];    // layer-0 h (plain), slice 0 zeros
__device__ float              g_h2[(size_t)(Tn + 1) * Bn * HP];    // layer-1 h (plain)
__device__ unsigned long long g_hd[(size_t)(Tn + 1) * Bn * HP];    // duplicated {h,h} pairs (slice 0 zeros)

// ---------------- helpers ----------------
__device__ __forceinline__ float sigf(float x) { return 1.f / (1.f + __expf(-x)); }
__device__ __forceinline__ float tanhfast(float x) { return 1.f - 2.f / (__expf(2.f * x) + 1.f); }

__device__ __forceinline__ unsigned long long pack2(float lo, float hi) {
    unsigned long long r;
    asm("mov.b64 %0, {%1, %2};" : "=l"(r) : "f"(lo), "f"(hi));
    return r;
}
__device__ __forceinline__ void unpack2(unsigned long long v, float& lo, float& hi) {
    asm("mov.b64 {%0, %1}, %2;" : "=f"(lo), "=f"(hi) : "l"(v));
}
__device__ __forceinline__ void ffma2(unsigned long long& acc, unsigned long long a, unsigned long long b) {
    asm("fma.rn.f32x2 %0, %1, %2, %0;" : "+l"(acc) : "l"(a), "l"(b));
}

// Transposed, gate-interleaved weight tile: sW[k*64 + m], m = u_local*4 + g.
__device__ void fill_WT(float* sW, const float* __restrict__ W, int u0, int Kreal, int kc_n) {
    int total = 64 * kc_n;
    for (int i = threadIdx.x; i < total; i += blockDim.x) {
        int m  = i / kc_n;
        int kc = i - m * kc_n;
        int k  = kc * 4;
        int g  = m & 3;
        int u  = u0 + (m >> 2);
        float4 v = make_float4(0.f, 0.f, 0.f, 0.f);
        if (u < Hn) {
            const float* src = W + (size_t)(g * Hn + u) * Kreal + k;
            if (k + 0 < Kreal) v.x = src[0];
            if (k + 1 < Kreal) v.y = src[1];
            if (k + 2 < Kreal) v.z = src[2];
            if (k + 3 < Kreal) v.w = src[3];
        }
        sW[(k + 0) * 64 + m] = v.x;
        sW[(k + 1) * 64 + m] = v.y;
        sW[(k + 2) * 64 + m] = v.z;
        sW[(k + 3) * 64 + m] = v.w;
    }
}

// ---------------- input-contribution GEMM (f32x2) ----------------
__global__ void __launch_bounds__(256, 1)
k_xgemm(const float* __restrict__ A_in, const float* __restrict__ Wih,
        const float* __restrict__ bih, const float* __restrict__ bhh,
        int amode, int Kreal, int kc_n) {
    extern __shared__ float smem[];
    float* sW = smem;                       // kc_n*4 * 64
    float* sA = sW + (size_t)kc_n * 4 * 64; // 64 * 260
    float* sB = sA + 64 * 260;              // 64 bias
    int tid = threadIdx.x;
    int u0 = blockIdx.y * 16;
    int rbase = blockIdx.x * 64;

    fill_WT(sW, Wih, u0, Kreal, kc_n);
    if (tid < 64) {
        int g = tid & 3, u = u0 + (tid >> 2);
        sB[tid] = (u < Hn) ? (bih[g * Hn + u] + bhh[g * Hn + u]) : 0.f;
    }
    if (amode == 1) {
        const float4* src = (const float4*)(g_h1 + ((size_t)rbase + Bn) * HP);
        for (int i = tid; i < 64 * 64; i += 256) {
            int row = i >> 6, c4 = i & 63;
            *(float4*)&sA[row * 260 + c4 * 4] = __ldg(src + (size_t)row * 64 + c4);
        }
    } else {
        for (int i = tid; i < 64 * 10; i += 256) {
            int row = i / 10, c4 = i - row * 10;
            int r = rbase + row;
            int tt = r >> 8, b = r & 255;
            *(float4*)&sA[row * 260 + c4 * 4] =
                __ldg((const float4*)(A_in + ((size_t)b * Tn + tt) * 40 + c4 * 4));
        }
    }
    __syncthreads();

    int q = tid & 15, rg = tid >> 4;
    int rl = rg * 4;
    unsigned long long a0_if = 0ull, a0_go = 0ull, a1_if = 0ull, a1_go = 0ull;
    unsigned long long a2_if = 0ull, a2_go = 0ull, a3_if = 0ull, a3_go = 0ull;

    #pragma unroll 3
    for (int kc = 0; kc < kc_n; ++kc) {
        int k = kc * 4;
        ulonglong2 w0 = *(const ulonglong2*)&sW[(k + 0) * 64 + 4 * q];
        ulonglong2 w1 = *(const ulonglong2*)&sW[(k + 1) * 64 + 4 * q];
        ulonglong2 w2 = *(const ulonglong2*)&sW[(k + 2) * 64 + 4 * q];
        ulonglong2 w3 = *(const ulonglong2*)&sW[(k + 3) * 64 + 4 * q];
#define XACC(AIF, AGO, ROW)                                                          \
        {                                                                            \
            float4 av = *(const float4*)&sA[(rl + ROW) * 260 + k];                   \
            unsigned long long h0 = pack2(av.x, av.x);                               \
            unsigned long long h1 = pack2(av.y, av.y);                               \
            unsigned long long h2 = pack2(av.z, av.z);                               \
            unsigned long long h3 = pack2(av.w, av.w);                               \
            ffma2(AIF, w0.x, h0); ffma2(AGO, w0.y, h0);                              \
            ffma2(AIF, w1.x, h1); ffma2(AGO, w1.y, h1);                              \
            ffma2(AIF, w2.x, h2); ffma2(AGO, w2.y, h2);                              \
            ffma2(AIF, w3.x, h3); ffma2(AGO, w3.y, h3);                              \
        }
        XACC(a0_if, a0_go, 0) XACC(a1_if, a1_go, 1) XACC(a2_if, a2_go, 2) XACC(a3_if, a3_go, 3)
#undef XACC
    }

    int u = u0 + q;
    if (u < Hn) {
        float4 bv = *(const float4*)&sB[4 * q];
#define XOUT(AIF, AGO, ROW)                                                          \
        {                                                                            \
            float4 o; float lo, hi;                                                  \
            unpack2(AIF, lo, hi); o.x = lo + bv.x; o.y = hi + bv.y;                  \
            unpack2(AGO, lo, hi); o.z = lo + bv.z; o.w = hi + bv.w;                  \
            *(float4*)(g_xg + ((size_t)(rbase + rl + ROW)) * Gn + u * 4) = o;        \
        }
        XOUT(a0_if, a0_go, 0) XOUT(a1_if, a1_go, 1) XOUT(a2_if, a2_go, 2) XOUT(a3_if, a3_go, 3)
#undef XOUT
    }
}

// ---------------- persistent recurrent kernel (clustered) ----------------
// 8 clusters x 16 CTAs. Cluster = one batch group of 32 columns; CTA = 16 units.
// Per step: stage packed {h,h} tile into smem, FFMA2 GEMM, pointwise, store h,
// then barrier.cluster (release/acquire) replaces fence+atomic+poll.
__global__ void __launch_bounds__(256, 1) __cluster_dims__(16, 1, 1)
k_rec(const float* __restrict__ Whh, int layer) {
    extern __shared__ float smem[];
    float* sW = smem;                                         // KP*64 floats (64512 B)
    unsigned long long* sH = (unsigned long long*)(smem + KP * 64);  // 32 rows * 252 u64 (64512 B)

    float* hplain = layer ? g_h2 : g_h1;
    const float* xg = g_xg;

    int tid = threadIdx.x;
    int ut = blockIdx.x & 15, bt = blockIdx.x >> 4;
    int u0 = ut * 16, b0 = bt * 32;
    int q = tid & 15, cg = tid >> 4, c0 = cg * 2;
    int u = u0 + q;
    bool valid = (u < Hn);

    fill_WT(sW, Whh, u0, Hn, KCn);

    float cv0 = 0.f, cv1 = 0.f;

    // prefetch xg for t=0
    float4 x0 = make_float4(0.f, 0.f, 0.f, 0.f), x1 = x0;
    if (valid) {
        size_t r0 = (size_t)0 * Bn + b0 + c0;
        x0 = __ldg((const float4*)(xg + r0 * Gn + u * 4));
        x1 = __ldg((const float4*)(xg + (r0 + 1) * Gn + u * 4));
    }
    __syncthreads();   // sW ready

    for (int t = 0; t < Tn; ++t) {
        // ---- stage packed h(t) tile [32 rows x 252 u64] from L2 into smem ----
        {
            const unsigned long long* src = g_hd + ((size_t)t * Bn + b0) * HP;
            for (int i = tid; i < 32 * 126; i += 256) {          // 126 ulonglong2 per row
                int row = i / 126, c2 = i - row * 126;
                ulonglong2 v = __ldcg((const ulonglong2*)(src + (size_t)row * HP + c2 * 2));
                *(ulonglong2*)&sH[row * KP + c2 * 2] = v;
            }
        }
        __syncthreads();

        // ---- gate GEMM: acc[2 cells][4 gates] via f32x2 ----
        unsigned long long A_if = 0ull, A_go = 0ull, B_if = 0ull, B_go = 0ull;
        const unsigned long long* rowA = &sH[(c0 + 0) * KP];
        const unsigned long long* rowB = &sH[(c0 + 1) * KP];

        #pragma unroll 9
        for (int kc = 0; kc < KCn; ++kc) {
            ulonglong2 w0 = *(const ulonglong2*)&sW[(kc * 4 + 0) * 64 + 4 * q];
            ulonglong2 w1 = *(const ulonglong2*)&sW[(kc * 4 + 1) * 64 + 4 * q];
            ulonglong2 w2 = *(const ulonglong2*)&sW[(kc * 4 + 2) * 64 + 4 * q];
            ulonglong2 w3 = *(const ulonglong2*)&sW[(kc * 4 + 3) * 64 + 4 * q];
            ulonglong2 alo = *(const ulonglong2*)&rowA[kc * 4];
            ulonglong2 ahi = *(const ulonglong2*)&rowA[kc * 4 + 2];
            ulonglong2 blo = *(const ulonglong2*)&rowB[kc * 4];
            ulonglong2 bhi = *(const ulonglong2*)&rowB[kc * 4 + 2];
            ffma2(A_if, w0.x, alo.x); ffma2(A_go, w0.y, alo.x);
            ffma2(A_if, w1.x, alo.y); ffma2(A_go, w1.y, alo.y);
            ffma2(A_if, w2.x, ahi.x); ffma2(A_go, w2.y, ahi.x);
            ffma2(A_if, w3.x, ahi.y); ffma2(A_go, w3.y, ahi.y);
            ffma2(B_if, w0.x, blo.x); ffma2(B_go, w0.y, blo.x);
            ffma2(B_if, w1.x, blo.y); ffma2(B_go, w1.y, blo.y);
            ffma2(B_if, w2.x, bhi.x); ffma2(B_go, w2.y, bhi.x);
            ffma2(B_if, w3.x, bhi.y); ffma2(B_go, w3.y, bhi.y);
        }

        // ---- pointwise LSTM cells + h stores ----
        {
            float gi, gf, gg, go;
            unpack2(A_if, gi, gf); unpack2(A_go, gg, go);
            float iv = sigf(gi + x0.x);
            float fv = sigf(gf + x0.y);
            float gv = tanhfast(gg + x0.z);
            float ov = sigf(go + x0.w);
            cv0 = fv * cv0 + iv * gv;
            float hv = ov * tanhfast(cv0);
            if (valid) {
                size_t w = ((size_t)(t + 1) * Bn + b0 + c0) * HP + u;
                __stcg(hplain + w, hv);
                __stcg((unsigned long long*)(g_hd + w), pack2(hv, hv));
            }
        }
        {
            float gi, gf, gg, go;
            unpack2(B_if, gi, gf); unpack2(B_go, gg, go);
            float iv = sigf(gi + x1.x);
            float fv = sigf(gf + x1.y);
            float gv = tanhfast(gg + x1.z);
            float ov = sigf(go + x1.w);
            cv1 = fv * cv1 + iv * gv;
            float hv = ov * tanhfast(cv1);
            if (valid) {
                size_t w = ((size_t)(t + 1) * Bn + b0 + c0 + 1) * HP + u;
                __stcg(hplain + w, hv);
                __stcg((unsigned long long*)(g_hd + w), pack2(hv, hv));
            }
        }

        // ---- cluster barrier: release h stores, acquire peers' ----
        asm volatile("barrier.cluster.arrive.aligned;" ::: "memory");
        // independent work inside the barrier window: prefetch next step's xg
        if (valid && t + 1 < Tn) {
            size_t r0 = (size_t)(t + 1) * Bn + b0 + c0;
            x0 = __ldg((const float4*)(xg + r0 * Gn + u * 4));
            x1 = __ldg((const float4*)(xg + (r0 + 1) * Gn + u * 4));
        }
        asm volatile("barrier.cluster.wait.aligned;" ::: "memory");
    }
}

// ---------------- output head ----------------
__global__ void __launch_bounds__(256, 1)
k_head(const float* __restrict__ Wl, const float* __restrict__ bl, float* __restrict__ out) {
    __shared__ float sw[256];
    int tid = threadIdx.x;
    sw[tid] = (tid < Hn) ? Wl[tid] : 0.f;
    __syncthreads();
    int warp = tid >> 5, lane = tid & 31;
    int r = blockIdx.x * 8 + warp;          // r = b*T + t
    int t = r & (Tn - 1);
    int b = r >> 9;
    const float* hrow = g_h2 + ((size_t)(t + 1) * Bn + b) * HP;
    float p = 0.f;
    #pragma unroll
    for (int j = 0; j < 8; ++j) {
        int k = j * 32 + lane;
        p = fmaf(sw[k], __ldg(hrow + k), p);
    }
    #pragma unroll
    for (int off = 16; off; off >>= 1) p += __shfl_xor_sync(0xffffffffu, p, off);
    if (lane == 0) out[r] = 1.f / (1.f + __expf(-(p + bl[0])));
}

// ---------------- launcher ----------------
extern "C" void kernel_launch(void* const* d_in, const int* in_sizes, int n_in,
                              void* d_out, int out_size) {
    const float* x    = (const float*)d_in[0];
    const float* Wih0 = (const float*)d_in[1];
    const float* Whh0 = (const float*)d_in[2];
    const float* bih0 = (const float*)d_in[3];
    const float* bhh0 = (const float*)d_in[4];
    const float* Wih1 = (const float*)d_in[5];
    const float* Whh1 = (const float*)d_in[6];
    const float* bih1 = (const float*)d_in[7];
    const float* bhh1 = (const float*)d_in[8];
    const float* Wlin = (const float*)d_in[9];
    const float* blin = (const float*)d_in[10];
    float* out = (float*)d_out;

    const int smem_rec   = (KP * 64) * 4 + 32 * KP * 8;            // 129,024 B
    const int smem_gemm1 = (KCn * 4 * 64 + 64 * 260 + 64) * 4;     // 131,328 B
    const int smem_gemm0 = (10 * 4 * 64 + 64 * 260 + 64) * 4;      // 77,056 B

    cudaFuncSetAttribute(k_rec,   cudaFuncAttributeMaxDynamicSharedMemorySize, smem_rec);
    cudaFuncSetAttribute(k_rec,   cudaFuncAttributeNonPortableClusterSizeAllowed, 1);
    cudaFuncSetAttribute(k_xgemm, cudaFuncAttributeMaxDynamicSharedMemorySize, smem_gemm1);

    // layer 0
    k_xgemm<<<dim3(2048, 16), 256, smem_gemm0>>>(x, Wih0, bih0, bhh0, 0, 40, 10);
    k_rec<<<128, 256, smem_rec>>>(Whh0, 0);

    // layer 1
    k_xgemm<<<dim3(2048, 16), 256, smem_gemm1>>>(nullptr, Wih1, bih1, bhh1, 1, Hn, KCn);
    k_rec<<<128, 256, smem_rec>>>(Whh1, 1);

    // head
    k_head<<<16384, 256>>>(Wlin, blin, out);
}

// round 7
// speedup vs baseline: 2.0138x; 2.0138x over previous
#include <cuda_runtime.h>
#include <cuda_bf16.h>
#include <cstdint>

#define Hn    250       // hidden units
#define Bn    256       // batch
#define Tn    512       // time steps
#define Gn    1000      // 4*H gate rows
#define HP    256       // padded hidden stride (elements / u64 pairs)
#define KP    252       // padded K for recurrent GEMM
#define KCn   63        // KP/4 chunks

// ---------------- scratch (device globals; zero-initialized at load) ----------------
__device__ float              g_xg[(size_t)Tn * Bn * Gn];          // input-gate contributions
__device__ float              g_h1[(size_t)(Tn + 1) * Bn * HP];    // layer-0 h plain (xgemm1 input), slice 0 zeros
__device__ unsigned long long g_hd[(size_t)(Tn + 1) * Bn * HP];    // duplicated {h,h} pairs (both layers reuse)
__device__ unsigned           g_cnt [2][8][32];                    // per-(layer, batch-group) monotone arrive counters
__device__ unsigned           g_flag[2][8][32];                    // per-(layer, batch-group) epoch flags

// ---------------- helpers ----------------
__device__ __forceinline__ float sigf(float x) { return 1.f / (1.f + __expf(-x)); }
__device__ __forceinline__ float tanhfast(float x) { return 1.f - 2.f / (__expf(2.f * x) + 1.f); }

__device__ __forceinline__ unsigned long long pack2(float lo, float hi) {
    unsigned long long r;
    asm("mov.b64 %0, {%1, %2};" : "=l"(r) : "f"(lo), "f"(hi));
    return r;
}
__device__ __forceinline__ void unpack2(unsigned long long v, float& lo, float& hi) {
    asm("mov.b64 {%0, %1}, %2;" : "=f"(lo), "=f"(hi) : "l"(v));
}
__device__ __forceinline__ void ffma2(unsigned long long& acc, unsigned long long a, unsigned long long b) {
    asm("fma.rn.f32x2 %0, %1, %2, %0;" : "+l"(acc) : "l"(a), "l"(b));
}

// Transposed, gate-interleaved weight tile: sW[k*64 + m], m = u_local*4 + g.
__device__ void fill_WT(float* sW, const float* __restrict__ W, int u0, int Kreal, int kc_n) {
    int total = 64 * kc_n;
    for (int i = threadIdx.x; i < total; i += blockDim.x) {
        int m  = i / kc_n;
        int kc = i - m * kc_n;
        int k  = kc * 4;
        int g  = m & 3;
        int u  = u0 + (m >> 2);
        float4 v = make_float4(0.f, 0.f, 0.f, 0.f);
        if (u < Hn) {
            const float* src = W + (size_t)(g * Hn + u) * Kreal + k;
            if (k + 0 < Kreal) v.x = src[0];
            if (k + 1 < Kreal) v.y = src[1];
            if (k + 2 < Kreal) v.z = src[2];
            if (k + 3 < Kreal) v.w = src[3];
        }
        sW[(k + 0) * 64 + m] = v.x;
        sW[(k + 1) * 64 + m] = v.y;
        sW[(k + 2) * 64 + m] = v.z;
        sW[(k + 3) * 64 + m] = v.w;
    }
}

__global__ void k_reset() {
    unsigned* c = &g_cnt[0][0][0];
    unsigned* f = &g_flag[0][0][0];
    for (int i = threadIdx.x; i < 2 * 8 * 32; i += blockDim.x) { c[i] = 0u; f[i] = 0u; }
}

// ---------------- input-contribution GEMM: 128 rows x 64 cols, 8-row register blocking ----------------
// grid: (16 col-tiles, BT/128 row-tiles). blockIdx.x = col tile (shares A across wave via L2).
__global__ void __launch_bounds__(256, 1)
k_xgemm(const float* __restrict__ A_in, const float* __restrict__ Wih,
        const float* __restrict__ bih, const float* __restrict__ bhh,
        int amode, int Kreal, int kc_n, int astride) {
    extern __shared__ float smem[];
    float* sW = smem;                          // kc_n*4 * 64
    float* sA = sW + (size_t)kc_n * 4 * 64;    // 128 * astride
    float* sB = sA + (size_t)128 * astride;    // 64 bias
    int tid = threadIdx.x;
    int u0 = blockIdx.x * 16;
    int rbase = blockIdx.y * 128;

    fill_WT(sW, Wih, u0, Kreal, kc_n);
    if (tid < 64) {
        int g = tid & 3, u = u0 + (tid >> 2);
        sB[tid] = (u < Hn) ? (bih[g * Hn + u] + bhh[g * Hn + u]) : 0.f;
    }
    if (amode == 1) {
        // A rows come from g_h1 at slice offset +Bn (h(t) lives in slot t+1)
        const float4* src = (const float4*)(g_h1 + ((size_t)rbase + Bn) * HP);
        for (int i = tid; i < 128 * 63; i += 256) {
            int row = i / 63, c4 = i - row * 63;
            *(float4*)&sA[row * astride + c4 * 4] = __ldg(src + (size_t)row * 64 + c4);
        }
    } else {
        for (int i = tid; i < 128 * 10; i += 256) {
            int row = i / 10, c4 = i - row * 10;
            int r = rbase + row;
            int tt = r >> 8, b = r & 255;
            *(float4*)&sA[row * astride + c4 * 4] =
                __ldg((const float4*)(A_in + ((size_t)b * Tn + tt) * 40 + c4 * 4));
        }
    }
    __syncthreads();

    int q = tid & 15, rg = tid >> 4;
    int r0 = rg * 8;
    unsigned long long acc_if[8], acc_go[8];
    #pragma unroll
    for (int rr = 0; rr < 8; ++rr) { acc_if[rr] = 0ull; acc_go[rr] = 0ull; }

    #pragma unroll 3
    for (int kc = 0; kc < kc_n; ++kc) {
        int k = kc * 4;
        ulonglong2 w0 = *(const ulonglong2*)&sW[(k + 0) * 64 + 4 * q];
        ulonglong2 w1 = *(const ulonglong2*)&sW[(k + 1) * 64 + 4 * q];
        ulonglong2 w2 = *(const ulonglong2*)&sW[(k + 2) * 64 + 4 * q];
        ulonglong2 w3 = *(const ulonglong2*)&sW[(k + 3) * 64 + 4 * q];
        #pragma unroll
        for (int rr = 0; rr < 8; ++rr) {
            float4 av = *(const float4*)&sA[(r0 + rr) * astride + k];
            unsigned long long h0 = pack2(av.x, av.x);
            unsigned long long h1 = pack2(av.y, av.y);
            unsigned long long h2 = pack2(av.z, av.z);
            unsigned long long h3 = pack2(av.w, av.w);
            ffma2(acc_if[rr], w0.x, h0); ffma2(acc_go[rr], w0.y, h0);
            ffma2(acc_if[rr], w1.x, h1); ffma2(acc_go[rr], w1.y, h1);
            ffma2(acc_if[rr], w2.x, h2); ffma2(acc_go[rr], w2.y, h2);
            ffma2(acc_if[rr], w3.x, h3); ffma2(acc_go[rr], w3.y, h3);
        }
    }

    int u = u0 + q;
    if (u < Hn) {
        float4 bv = *(const float4*)&sB[4 * q];
        #pragma unroll
        for (int rr = 0; rr < 8; ++rr) {
            float4 o; float lo, hi;
            unpack2(acc_if[rr], lo, hi); o.x = lo + bv.x; o.y = hi + bv.y;
            unpack2(acc_go[rr], lo, hi); o.z = lo + bv.z; o.w = hi + bv.w;
            *(float4*)(g_xg + ((size_t)(rbase + r0 + rr)) * Gn + u * 4) = o;
        }
    }
}

// ---------------- persistent recurrent kernel ----------------
// 128 CTAs = 16 unit-tiles x 8 batch-groups. Thread: unit q = tid&15, batch cols c0,c0+1.
// Per-warp staging of its own 4 h-rows (packed {h,h}) -> __syncwarp only.
// Per-group (16-CTA) monotone-epoch atomic barrier, CG-style leader fence.
__global__ void __launch_bounds__(256, 1)
k_rec(const float* __restrict__ Whh, int layer) {
    extern __shared__ float smem[];
    float* sW = smem;                                               // KP*64 floats (64512 B)
    unsigned long long* sH = (unsigned long long*)(smem + KP * 64); // 32 rows * 252 u64 (64512 B)

    const float* xg = g_xg;

    int tid = threadIdx.x, lane = tid & 31, w = tid >> 5;
    int ut = blockIdx.x & 15, bt = blockIdx.x >> 4;
    int u0 = ut * 16, b0 = bt * 32;
    int q = tid & 15, cg = tid >> 4, c0 = cg * 2;
    int u = u0 + q;
    bool valid = (u < Hn);

    unsigned* cnt = &g_cnt[layer][bt][0];
    unsigned* flg = &g_flag[layer][bt][0];

    fill_WT(sW, Whh, u0, Hn, KCn);

    float cv0 = 0.f, cv1 = 0.f;
    __syncthreads();   // sW ready (read-only afterwards)

    for (int t = 0; t < Tn; ++t) {
        // prefetch xg contributions for this step (overlaps staging latency)
        float4 x0 = make_float4(0.f, 0.f, 0.f, 0.f), x1 = x0;
        if (valid) {
            size_t r0i = (size_t)t * Bn + b0 + c0;
            x0 = __ldg((const float4*)(xg + r0i * Gn + u * 4));
            x1 = __ldg((const float4*)(xg + (r0i + 1) * Gn + u * 4));
        }

        // ---- per-warp stage of rows 4w..4w+3 (the only rows this warp reads) ----
        {
            const unsigned long long* src = g_hd + ((size_t)t * Bn + b0 + 4 * w) * HP;
            #pragma unroll
            for (int j = 0; j < 16; ++j) {
                int i = j * 32 + lane;                 // 0..511, need < 504
                if (i < 504) {
                    int row = i / 126, c2 = i - row * 126;
                    ulonglong2 v = __ldcg((const ulonglong2*)(src + (size_t)row * HP + c2 * 2));
                    *(ulonglong2*)&sH[(4 * w + row) * KP + c2 * 2] = v;
                }
            }
        }
        __syncwarp();

        // ---- gate GEMM: acc[2 cells][4 gates] via f32x2 ----
        unsigned long long A_if = 0ull, A_go = 0ull, B_if = 0ull, B_go = 0ull;
        const unsigned long long* rowA = &sH[(c0 + 0) * KP];
        const unsigned long long* rowB = &sH[(c0 + 1) * KP];

        #pragma unroll 9
        for (int kc = 0; kc < KCn; ++kc) {
            ulonglong2 w0 = *(const ulonglong2*)&sW[(kc * 4 + 0) * 64 + 4 * q];
            ulonglong2 w1 = *(const ulonglong2*)&sW[(kc * 4 + 1) * 64 + 4 * q];
            ulonglong2 w2 = *(const ulonglong2*)&sW[(kc * 4 + 2) * 64 + 4 * q];
            ulonglong2 w3 = *(const ulonglong2*)&sW[(kc * 4 + 3) * 64 + 4 * q];
            ulonglong2 alo = *(const ulonglong2*)&rowA[kc * 4];
            ulonglong2 ahi = *(const ulonglong2*)&rowA[kc * 4 + 2];
            ulonglong2 blo = *(const ulonglong2*)&rowB[kc * 4];
            ulonglong2 bhi = *(const ulonglong2*)&rowB[kc * 4 + 2];
            ffma2(A_if, w0.x, alo.x); ffma2(A_go, w0.y, alo.x);
            ffma2(A_if, w1.x, alo.y); ffma2(A_go, w1.y, alo.y);
            ffma2(A_if, w2.x, ahi.x); ffma2(A_go, w2.y, ahi.x);
            ffma2(A_if, w3.x, ahi.y); ffma2(A_go, w3.y, ahi.y);
            ffma2(B_if, w0.x, blo.x); ffma2(B_go, w0.y, blo.x);
            ffma2(B_if, w1.x, blo.y); ffma2(B_go, w1.y, blo.y);
            ffma2(B_if, w2.x, bhi.x); ffma2(B_go, w2.y, bhi.x);
            ffma2(B_if, w3.x, bhi.y); ffma2(B_go, w3.y, bhi.y);
        }

        // ---- pointwise LSTM cells + h stores ----
        {
            float gi, gf, gg, go;
            unpack2(A_if, gi, gf); unpack2(A_go, gg, go);
            float iv = sigf(gi + x0.x);
            float fv = sigf(gf + x0.y);
            float gv = tanhfast(gg + x0.z);
            float ov = sigf(go + x0.w);
            cv0 = fv * cv0 + iv * gv;
            float hv = ov * tanhfast(cv0);
            if (valid) {
                size_t wi = ((size_t)(t + 1) * Bn + b0 + c0) * HP + u;
                __stcg((unsigned long long*)(g_hd + wi), pack2(hv, hv));
                if (layer == 0) __stcg(g_h1 + wi, hv);
            }
        }
        {
            float gi, gf, gg, go;
            unpack2(B_if, gi, gf); unpack2(B_go, gg, go);
            float iv = sigf(gi + x1.x);
            float fv = sigf(gf + x1.y);
            float gv = tanhfast(gg + x1.z);
            float ov = sigf(go + x1.w);
            cv1 = fv * cv1 + iv * gv;
            float hv = ov * tanhfast(cv1);
            if (valid) {
                size_t wi = ((size_t)(t + 1) * Bn + b0 + c0 + 1) * HP + u;
                __stcg((unsigned long long*)(g_hd + wi), pack2(hv, hv));
                if (layer == 0) __stcg(g_h1 + wi, hv);
            }
        }

        // ---- 16-CTA group barrier: monotone epoch counter, CG-style leader protocol ----
        __syncthreads();
        if (tid == 0) {
            __threadfence();                          // cumulative release of CTA's stores
            unsigned old = atomicAdd(cnt, 1u);
            unsigned epoch = (unsigned)(t + 1);
            if ((old & 15u) == 15u) {
                asm volatile("st.release.gpu.b32 [%0], %1;" :: "l"(flg), "r"(epoch) : "memory");
            }
            unsigned v;
            do {
                asm volatile("ld.acquire.gpu.b32 %0, [%1];" : "=r"(v) : "l"(flg) : "memory");
            } while (v < epoch);
        }
        __syncthreads();
    }
}

// ---------------- output head (reads packed h2) ----------------
__global__ void __launch_bounds__(256, 1)
k_head(const float* __restrict__ Wl, const float* __restrict__ bl, float* __restrict__ out) {
    __shared__ float sw[256];
    int tid = threadIdx.x;
    sw[tid] = (tid < Hn) ? Wl[tid] : 0.f;
    __syncthreads();
    int warp = tid >> 5, lane = tid & 31;
    int r = blockIdx.x * 8 + warp;          // r = b*T + t (output order)
    int t = r & (Tn - 1);
    int b = r >> 9;
    const unsigned long long* hrow = g_hd + ((size_t)(t + 1) * Bn + b) * HP;
    float p = 0.f;
    #pragma unroll
    for (int j = 0; j < 8; ++j) {
        int k = j * 32 + lane;
        float lo, hi;
        unpack2(__ldg(hrow + k), lo, hi);
        p = fmaf(sw[k], lo, p);
    }
    #pragma unroll
    for (int off = 16; off; off >>= 1) p += __shfl_xor_sync(0xffffffffu, p, off);
    if (lane == 0) out[r] = 1.f / (1.f + __expf(-(p + bl[0])));
}

// ---------------- launcher ----------------
extern "C" void kernel_launch(void* const* d_in, const int* in_sizes, int n_in,
                              void* d_out, int out_size) {
    const float* x    = (const float*)d_in[0];
    const float* Wih0 = (const float*)d_in[1];
    const float* Whh0 = (const float*)d_in[2];
    const float* bih0 = (const float*)d_in[3];
    const float* bhh0 = (const float*)d_in[4];
    const float* Wih1 = (const float*)d_in[5];
    const float* Whh1 = (const float*)d_in[6];
    const float* bih1 = (const float*)d_in[7];
    const float* bhh1 = (const float*)d_in[8];
    const float* Wlin = (const float*)d_in[9];
    const float* blin = (const float*)d_in[10];
    float* out = (float*)d_out;

    const int smem_rec   = (KP * 64) * 4 + 32 * KP * 8;               // 129,024 B
    const int smem_gemm1 = (KCn * 4 * 64 + 128 * 260 + 64) * 4;       // 197,888 B
    const int smem_gemm0 = (10 * 4 * 64 + 128 * 48 + 64) * 4;         // 35,072 B

    cudaFuncSetAttribute(k_rec,   cudaFuncAttributeMaxDynamicSharedMemorySize, smem_rec);
    cudaFuncSetAttribute(k_xgemm, cudaFuncAttributeMaxDynamicSharedMemorySize, smem_gemm1);

    k_reset<<<1, 256>>>();

    // layer 0
    k_xgemm<<<dim3(16, 1024), 256, smem_gemm0>>>(x, Wih0, bih0, bhh0, 0, 40, 10, 48);
    k_rec<<<128, 256, smem_rec>>>(Whh0, 0);

    // layer 1
    k_xgemm<<<dim3(16, 1024), 256, smem_gemm1>>>(nullptr, Wih1, bih1, bhh1, 1, Hn, KCn, 260);
    k_rec<<<128, 256, smem_rec>>>(Whh1, 1);

    // head
    k_head<<<16384, 256>>>(Wlin, blin, out);
}

// round 9
// speedup vs baseline: 2.1491x; 1.0672x over previous
#include <cuda_runtime.h>
#include <cuda_bf16.h>
#include <cstdint>

#define Hn    250       // hidden units
#define Bn    256       // batch
#define Tn    512       // time steps
#define Gn    1000      // 4*H gate rows
#define HP    256       // padded hidden stride (elements / u64 pairs)
#define KP    252       // padded K for recurrent GEMM
#define KCn   63        // KP/4 chunks

// ---------------- scratch (device globals; zero-initialized at load) ----------------
__device__ float              g_xg[(size_t)Tn * Bn * Gn];          // input-gate contributions
__device__ float              g_h1[(size_t)(Tn + 1) * Bn * HP];    // layer-0 h plain (xgemm1 input), slice 0 zeros
__device__ unsigned long long g_hd[(size_t)(Tn + 1) * Bn * HP];    // duplicated {h,h} pairs (both layers reuse)
__device__ unsigned           g_cnt [2][16][32];                   // per-(layer, col-group) monotone arrive counters
__device__ unsigned           g_flag[2][16][32];                   // per-(layer, col-group) epoch flags

// ---------------- helpers ----------------
__device__ __forceinline__ float sigf(float x) { return 1.f / (1.f + __expf(-x)); }
__device__ __forceinline__ float tanhfast(float x) { return 1.f - 2.f / (__expf(2.f * x) + 1.f); }

__device__ __forceinline__ unsigned long long pack2(float lo, float hi) {
    unsigned long long r;
    asm("mov.b64 %0, {%1, %2};" : "=l"(r) : "f"(lo), "f"(hi));
    return r;
}
__device__ __forceinline__ void unpack2(unsigned long long v, float& lo, float& hi) {
    asm("mov.b64 {%0, %1}, %2;" : "=f"(lo), "=f"(hi) : "l"(v));
}
__device__ __forceinline__ void ffma2(unsigned long long& acc, unsigned long long a, unsigned long long b) {
    asm("fma.rn.f32x2 %0, %1, %2, %0;" : "+l"(acc) : "l"(a), "l"(b));
}

// Transposed, gate-interleaved weight tile: sW[k*64 + m], m = u_local*4 + g.
__device__ void fill_WT(float* sW, const float* __restrict__ W, int u0, int Kreal, int kc_n) {
    int total = 64 * kc_n;
    for (int i = threadIdx.x; i < total; i += blockDim.x) {
        int m  = i / kc_n;
        int kc = i - m * kc_n;
        int k  = kc * 4;
        int g  = m & 3;
        int u  = u0 + (m >> 2);
        float4 v = make_float4(0.f, 0.f, 0.f, 0.f);
        if (u < Hn) {
            const float* src = W + (size_t)(g * Hn + u) * Kreal + k;
            if (k + 0 < Kreal) v.x = src[0];
            if (k + 1 < Kreal) v.y = src[1];
            if (k + 2 < Kreal) v.z = src[2];
            if (k + 3 < Kreal) v.w = src[3];
        }
        sW[(k + 0) * 64 + m] = v.x;
        sW[(k + 1) * 64 + m] = v.y;
        sW[(k + 2) * 64 + m] = v.z;
        sW[(k + 3) * 64 + m] = v.w;
    }
}

__global__ void k_reset() {
    unsigned* c = &g_cnt[0][0][0];
    unsigned* f = &g_flag[0][0][0];
    for (int i = threadIdx.x; i < 2 * 16 * 32; i += blockDim.x) { c[i] = 0u; f[i] = 0u; }
}

// ---------------- input-contribution GEMM: 128 rows x 64 cols, 8-row register blocking ----------------
__global__ void __launch_bounds__(256, 1)
k_xgemm(const float* __restrict__ A_in, const float* __restrict__ Wih,
        const float* __restrict__ bih, const float* __restrict__ bhh,
        int amode, int Kreal, int kc_n, int astride) {
    extern __shared__ float smem[];
    float* sW = smem;                          // kc_n*4 * 64
    float* sA = sW + (size_t)kc_n * 4 * 64;    // 128 * astride
    float* sB = sA + (size_t)128 * astride;    // 64 bias
    int tid = threadIdx.x;
    int u0 = blockIdx.x * 16;
    int rbase = blockIdx.y * 128;

    fill_WT(sW, Wih, u0, Kreal, kc_n);
    if (tid < 64) {
        int g = tid & 3, u = u0 + (tid >> 2);
        sB[tid] = (u < Hn) ? (bih[g * Hn + u] + bhh[g * Hn + u]) : 0.f;
    }
    if (amode == 1) {
        const float4* src = (const float4*)(g_h1 + ((size_t)rbase + Bn) * HP);
        for (int i = tid; i < 128 * 63; i += 256) {
            int row = i / 63, c4 = i - row * 63;
            *(float4*)&sA[row * astride + c4 * 4] = __ldg(src + (size_t)row * 64 + c4);
        }
    } else {
        for (int i = tid; i < 128 * 10; i += 256) {
            int row = i / 10, c4 = i - row * 10;
            int r = rbase + row;
            int tt = r >> 8, b = r & 255;
            *(float4*)&sA[row * astride + c4 * 4] =
                __ldg((const float4*)(A_in + ((size_t)b * Tn + tt) * 40 + c4 * 4));
        }
    }
    __syncthreads();

    int q = tid & 15, rg = tid >> 4;
    int r0 = rg * 8;
    unsigned long long acc_if[8], acc_go[8];
    #pragma unroll
    for (int rr = 0; rr < 8; ++rr) { acc_if[rr] = 0ull; acc_go[rr] = 0ull; }

    #pragma unroll 3
    for (int kc = 0; kc < kc_n; ++kc) {
        int k = kc * 4;
        ulonglong2 w0 = *(const ulonglong2*)&sW[(k + 0) * 64 + 4 * q];
        ulonglong2 w1 = *(const ulonglong2*)&sW[(k + 1) * 64 + 4 * q];
        ulonglong2 w2 = *(const ulonglong2*)&sW[(k + 2) * 64 + 4 * q];
        ulonglong2 w3 = *(const ulonglong2*)&sW[(k + 3) * 64 + 4 * q];
        #pragma unroll
        for (int rr = 0; rr < 8; ++rr) {
            float4 av = *(const float4*)&sA[(r0 + rr) * astride + k];
            unsigned long long h0 = pack2(av.x, av.x);
            unsigned long long h1 = pack2(av.y, av.y);
            unsigned long long h2 = pack2(av.z, av.z);
            unsigned long long h3 = pack2(av.w, av.w);
            ffma2(acc_if[rr], w0.x, h0); ffma2(acc_go[rr], w0.y, h0);
            ffma2(acc_if[rr], w1.x, h1); ffma2(acc_go[rr], w1.y, h1);
            ffma2(acc_if[rr], w2.x, h2); ffma2(acc_go[rr], w2.y, h2);
            ffma2(acc_if[rr], w3.x, h3); ffma2(acc_go[rr], w3.y, h3);
        }
    }

    int u = u0 + q;
    if (u < Hn) {
        float4 bv = *(const float4*)&sB[4 * q];
        #pragma unroll
        for (int rr = 0; rr < 8; ++rr) {
            float4 o; float lo, hi;
            unpack2(acc_if[rr], lo, hi); o.x = lo + bv.x; o.y = hi + bv.y;
            unpack2(acc_go[rr], lo, hi); o.z = lo + bv.z; o.w = hi + bv.w;
            *(float4*)(g_xg + ((size_t)(rbase + r0 + rr)) * Gn + u * 4) = o;
        }
    }
}

// ---------------- persistent recurrent kernel: 2 CTAs/SM for latency overlap ----------------
// 256 CTAs = 16 unit-tiles x 16 col-groups (16 cols each). 128 threads (4 warps).
// Thread: unit q = tid&15, colpair cg = tid>>4 (c0 = 2*cg). smem 96.8KB -> 2 CTAs/SM;
// co-resident CTAs are in different barrier groups, so barrier/staging latency of one
// overlaps with the other's FFMA2 stream.
__global__ void __launch_bounds__(128, 2)
k_rec(const float* __restrict__ Whh, int layer) {
    extern __shared__ float smem[];
    float* sW = smem;                                               // KP*64 floats (64512 B)
    unsigned long long* sH = (unsigned long long*)(smem + KP * 64); // 16 rows * 252 u64 (32256 B)

    const float* xg = g_xg;

    int tid = threadIdx.x, lane = tid & 31, w = tid >> 5;
    int ut = blockIdx.x & 15, grp = blockIdx.x >> 4;
    int u0 = ut * 16, b0 = grp * 16;
    int q = tid & 15, cg = tid >> 4, c0 = cg * 2;
    int u = u0 + q;
    bool valid = (u < Hn);

    unsigned* cnt = &g_cnt[layer][grp][0];
    unsigned* flg = &g_flag[layer][grp][0];

    fill_WT(sW, Whh, u0, Hn, KCn);

    float cv0 = 0.f, cv1 = 0.f;
    __syncthreads();   // sW ready (read-only afterwards)

    for (int t = 0; t < Tn; ++t) {
        // prefetch xg contributions for this step
        float4 x0 = make_float4(0.f, 0.f, 0.f, 0.f), x1 = x0;
        if (valid) {
            size_t r0i = (size_t)t * Bn + b0 + c0;
            x0 = __ldg((const float4*)(xg + r0i * Gn + u * 4));
            x1 = __ldg((const float4*)(xg + (r0i + 1) * Gn + u * 4));
        }

        // ---- per-warp stage of sH rows 4w..4w+3 (packed {h,h}) ----
        {
            const unsigned long long* src = g_hd + ((size_t)t * Bn + b0 + 4 * w) * HP;
            #pragma unroll
            for (int j = 0; j < 16; ++j) {
                int i = j * 32 + lane;                 // 0..511, need < 504
                if (i < 504) {
                    int row = i / 126, c2 = i - row * 126;
                    ulonglong2 v = __ldcg((const ulonglong2*)(src + (size_t)row * HP + c2 * 2));
                    *(ulonglong2*)&sH[(4 * w + row) * KP + c2 * 2] = v;
                }
            }
        }
        __syncwarp();

        // ---- gate GEMM: acc[2 cells][4 gates] via f32x2 ----
        unsigned long long A_if = 0ull, A_go = 0ull, B_if = 0ull, B_go = 0ull;
        const unsigned long long* rowA = &sH[(c0 + 0) * KP];
        const unsigned long long* rowB = &sH[(c0 + 1) * KP];

        #pragma unroll 9
        for (int kc = 0; kc < KCn; ++kc) {
            ulonglong2 w0 = *(const ulonglong2*)&sW[(kc * 4 + 0) * 64 + 4 * q];
            ulonglong2 w1 = *(const ulonglong2*)&sW[(kc * 4 + 1) * 64 + 4 * q];
            ulonglong2 w2 = *(const ulonglong2*)&sW[(kc * 4 + 2) * 64 + 4 * q];
            ulonglong2 w3 = *(const ulonglong2*)&sW[(kc * 4 + 3) * 64 + 4 * q];
            ulonglong2 alo = *(const ulonglong2*)&rowA[kc * 4];
            ulonglong2 ahi = *(const ulonglong2*)&rowA[kc * 4 + 2];
            ulonglong2 blo = *(const ulonglong2*)&rowB[kc * 4];
            ulonglong2 bhi = *(const ulonglong2*)&rowB[kc * 4 + 2];
            ffma2(A_if, w0.x, alo.x); ffma2(A_go, w0.y, alo.x);
            ffma2(A_if, w1.x, alo.y); ffma2(A_go, w1.y, alo.y);
            ffma2(A_if, w2.x, ahi.x); ffma2(A_go, w2.y, ahi.x);
            ffma2(A_if, w3.x, ahi.y); ffma2(A_go, w3.y, ahi.y);
            ffma2(B_if, w0.x, blo.x); ffma2(B_go, w0.y, blo.x);
            ffma2(B_if, w1.x, blo.y); ffma2(B_go, w1.y, blo.y);
            ffma2(B_if, w2.x, bhi.x); ffma2(B_go, w2.y, bhi.x);
            ffma2(B_if, w3.x, bhi.y); ffma2(B_go, w3.y, bhi.y);
        }

        // ---- pointwise LSTM cells + h stores ----
        {
            float gi, gf, gg, go;
            unpack2(A_if, gi, gf); unpack2(A_go, gg, go);
            float iv = sigf(gi + x0.x);
            float fv = sigf(gf + x0.y);
            float gv = tanhfast(gg + x0.z);
            float ov = sigf(go + x0.w);
            cv0 = fv * cv0 + iv * gv;
            float hv = ov * tanhfast(cv0);
            if (valid) {
                size_t wi = ((size_t)(t + 1) * Bn + b0 + c0) * HP + u;
                __stcg((unsigned long long*)(g_hd + wi), pack2(hv, hv));
                if (layer == 0) __stcg(g_h1 + wi, hv);
            }
        }
        {
            float gi, gf, gg, go;
            unpack2(B_if, gi, gf); unpack2(B_go, gg, go);
            float iv = sigf(gi + x1.x);
            float fv = sigf(gf + x1.y);
            float gv = tanhfast(gg + x1.z);
            float ov = sigf(go + x1.w);
            cv1 = fv * cv1 + iv * gv;
            float hv = ov * tanhfast(cv1);
            if (valid) {
                size_t wi = ((size_t)(t + 1) * Bn + b0 + c0 + 1) * HP + u;
                __stcg((unsigned long long*)(g_hd + wi), pack2(hv, hv));
                if (layer == 0) __stcg(g_h1 + wi, hv);
            }
        }

        // ---- 16-CTA group barrier: monotone epoch counter (proven R7 protocol) ----
        __syncthreads();
        if (tid == 0) {
            __threadfence();                          // cumulative release of CTA's stores
            unsigned old = atomicAdd(cnt, 1u);
            unsigned epoch = (unsigned)(t + 1);
            if ((old & 15u) == 15u) {
                asm volatile("st.release.gpu.b32 [%0], %1;" :: "l"(flg), "r"(epoch) : "memory");
            }
            unsigned v;
            do {
                asm volatile("ld.acquire.gpu.b32 %0, [%1];" : "=r"(v) : "l"(flg) : "memory");
            } while (v < epoch);
        }
        __syncthreads();
    }
}

// ---------------- output head (reads packed h2) ----------------
__global__ void __launch_bounds__(256, 1)
k_head(const float* __restrict__ Wl, const float* __restrict__ bl, float* __restrict__ out) {
    __shared__ float sw[256];
    int tid = threadIdx.x;
    sw[tid] = (tid < Hn) ? Wl[tid] : 0.f;
    __syncthreads();
    int warp = tid >> 5, lane = tid & 31;
    int r = blockIdx.x * 8 + warp;          // r = b*T + t (output order)
    int t = r & (Tn - 1);
    int b = r >> 9;
    const unsigned long long* hrow = g_hd + ((size_t)(t + 1) * Bn + b) * HP;
    float p = 0.f;
    #pragma unroll
    for (int j = 0; j < 8; ++j) {
        int k = j * 32 + lane;
        float lo, hi;
        unpack2(__ldg(hrow + k), lo, hi);
        p = fmaf(sw[k], lo, p);
    }
    #pragma unroll
    for (int off = 16; off; off >>= 1) p += __shfl_xor_sync(0xffffffffu, p, off);
    if (lane == 0) out[r] = 1.f / (1.f + __expf(-(p + bl[0])));
}

// ---------------- launcher ----------------
extern "C" void kernel_launch(void* const* d_in, const int* in_sizes, int n_in,
                              void* d_out, int out_size) {
    const float* x    = (const float*)d_in[0];
    const float* Wih0 = (const float*)d_in[1];
    const float* Whh0 = (const float*)d_in[2];
    const float* bih0 = (const float*)d_in[3];
    const float* bhh0 = (const float*)d_in[4];
    const float* Wih1 = (const float*)d_in[5];
    const float* Whh1 = (const float*)d_in[6];
    const float* bih1 = (const float*)d_in[7];
    const float* bhh1 = (const float*)d_in[8];
    const float* Wlin = (const float*)d_in[9];
    const float* blin = (const float*)d_in[10];
    float* out = (float*)d_out;

    const int smem_rec   = (KP * 64) * 4 + 16 * KP * 8;               // 96,768 B -> 2 CTAs/SM
    const int smem_gemm1 = (KCn * 4 * 64 + 128 * 260 + 64) * 4;       // 197,888 B
    const int smem_gemm0 = (10 * 4 * 64 + 128 * 48 + 64) * 4;         // 35,072 B

    cudaFuncSetAttribute(k_rec,   cudaFuncAttributeMaxDynamicSharedMemorySize, smem_rec);
    cudaFuncSetAttribute(k_xgemm, cudaFuncAttributeMaxDynamicSharedMemorySize, smem_gemm1);

    k_reset<<<1, 256>>>();

    // layer 0
    k_xgemm<<<dim3(16, 1024), 256, smem_gemm0>>>(x, Wih0, bih0, bhh0, 0, 40, 10, 48);
    k_rec<<<256, 128, smem_rec>>>(Whh0, 0);

    // layer 1
    k_xgemm<<<dim3(16, 1024), 256, smem_gemm1>>>(nullptr, Wih1, bih1, bhh1, 1, Hn, KCn, 260);
    k_rec<<<256, 128, smem_rec>>>(Whh1, 1);

    // head
    k_head<<<16384, 256>>>(Wlin, blin, out);
}

// round 13
// speedup vs baseline: 2.3311x; 1.0847x over previous
#include <cuda_runtime.h>
#include <cuda_bf16.h>
#include <cstdint>

#define Hn    250       // hidden units
#define Bn    256       // batch
#define Tn    512       // time steps
#define Gn    1000      // 4*H gate rows
#define HP    256       // padded hidden stride (elements / u64 pairs)
#define KP    252       // padded K for recurrent GEMM
#define KCn   63        // KP/4 chunks

// ---------------- scratch (device globals; zero-initialized at load) ----------------
__device__ float              g_xg[(size_t)Tn * Bn * Gn];          // input-gate contributions
__device__ float              g_h1[(size_t)(Tn + 1) * Bn * HP];    // layer-0 h plain (xgemm1 input), slice 0 zeros
__device__ unsigned long long g_hd[(size_t)(Tn + 1) * Bn * HP];    // duplicated {h,h} pairs (both layers reuse)
__device__ unsigned           g_cnt [2][8][32];                    // per-(layer, batch-group) monotone arrive counters
__device__ unsigned           g_flag[2][8][32];                    // per-(layer, batch-group) monotone epoch flags

// ---------------- helpers ----------------
__device__ __forceinline__ float sigf(float x) { return 1.f / (1.f + __expf(-x)); }
__device__ __forceinline__ float tanhfast(float x) { return 1.f - 2.f / (__expf(2.f * x) + 1.f); }

__device__ __forceinline__ unsigned long long pack2(float lo, float hi) {
    unsigned long long r;
    asm("mov.b64 %0, {%1, %2};" : "=l"(r) : "f"(lo), "f"(hi));
    return r;
}
__device__ __forceinline__ void unpack2(unsigned long long v, float& lo, float& hi) {
    asm("mov.b64 {%0, %1}, %2;" : "=f"(lo), "=f"(hi) : "l"(v));
}
__device__ __forceinline__ void ffma2(unsigned long long& acc, unsigned long long a, unsigned long long b) {
    asm("fma.rn.f32x2 %0, %1, %2, %0;" : "+l"(acc) : "l"(a), "l"(b));
}
__device__ __forceinline__ unsigned long long add2(unsigned long long a, unsigned long long b) {
    unsigned long long r;
    asm("add.rn.f32x2 %0, %1, %2;" : "=l"(r) : "l"(a), "l"(b));
    return r;
}

// Transposed, gate-interleaved weight tile: sW[k*64 + m], m = u_local*4 + g.
__device__ void fill_WT(float* sW, const float* __restrict__ W, int u0, int Kreal, int kc_n) {
    int total = 64 * kc_n;
    for (int i = threadIdx.x; i < total; i += blockDim.x) {
        int m  = i / kc_n;
        int kc = i - m * kc_n;
        int k  = kc * 4;
        int g  = m & 3;
        int u  = u0 + (m >> 2);
        float4 v = make_float4(0.f, 0.f, 0.f, 0.f);
        if (u < Hn) {
            const float* src = W + (size_t)(g * Hn + u) * Kreal + k;
            if (k + 0 < Kreal) v.x = src[0];
            if (k + 1 < Kreal) v.y = src[1];
            if (k + 2 < Kreal) v.z = src[2];
            if (k + 3 < Kreal) v.w = src[3];
        }
        sW[(k + 0) * 64 + m] = v.x;
        sW[(k + 1) * 64 + m] = v.y;
        sW[(k + 2) * 64 + m] = v.z;
        sW[(k + 3) * 64 + m] = v.w;
    }
}

// ---------------- input-contribution GEMM: 128 rows x 64 cols, 8-row register blocking ----------------
__global__ void __launch_bounds__(256, 1)
k_xgemm(const float* __restrict__ A_in, const float* __restrict__ Wih,
        const float* __restrict__ bih, const float* __restrict__ bhh,
        int amode, int Kreal, int kc_n, int astride) {
    extern __shared__ float smem[];
    float* sW = smem;                          // kc_n*4 * 64
    float* sA = sW + (size_t)kc_n * 4 * 64;    // 128 * astride
    float* sB = sA + (size_t)128 * astride;    // 64 bias
    int tid = threadIdx.x;
    int u0 = blockIdx.x * 16;
    int rbase = blockIdx.y * 128;

    fill_WT(sW, Wih, u0, Kreal, kc_n);
    if (tid < 64) {
        int g = tid & 3, u = u0 + (tid >> 2);
        sB[tid] = (u < Hn) ? (bih[g * Hn + u] + bhh[g * Hn + u]) : 0.f;
    }
    if (amode == 1) {
        const float4* src = (const float4*)(g_h1 + ((size_t)rbase + Bn) * HP);
        for (int i = tid; i < 128 * 63; i += 256) {
            int row = i / 63, c4 = i - row * 63;
            *(float4*)&sA[row * astride + c4 * 4] = __ldg(src + (size_t)row * 64 + c4);
        }
    } else {
        for (int i = tid; i < 128 * 10; i += 256) {
            int row = i / 10, c4 = i - row * 10;
            int r = rbase + row;
            int tt = r >> 8, b = r & 255;
            *(float4*)&sA[row * astride + c4 * 4] =
                __ldg((const float4*)(A_in + ((size_t)b * Tn + tt) * 40 + c4 * 4));
        }
    }
    __syncthreads();

    int q = tid & 15, rg = tid >> 4;
    int r0 = rg * 8;
    unsigned long long acc_if[8], acc_go[8];
    #pragma unroll
    for (int rr = 0; rr < 8; ++rr) { acc_if[rr] = 0ull; acc_go[rr] = 0ull; }

    #pragma unroll 3
    for (int kc = 0; kc < kc_n; ++kc) {
        int k = kc * 4;
        ulonglong2 w0 = *(const ulonglong2*)&sW[(k + 0) * 64 + 4 * q];
        ulonglong2 w1 = *(const ulonglong2*)&sW[(k + 1) * 64 + 4 * q];
        ulonglong2 w2 = *(const ulonglong2*)&sW[(k + 2) * 64 + 4 * q];
        ulonglong2 w3 = *(const ulonglong2*)&sW[(k + 3) * 64 + 4 * q];
        #pragma unroll
        for (int rr = 0; rr < 8; ++rr) {
            float4 av = *(const float4*)&sA[(r0 + rr) * astride + k];
            unsigned long long h0 = pack2(av.x, av.x);
            unsigned long long h1 = pack2(av.y, av.y);
            unsigned long long h2 = pack2(av.z, av.z);
            unsigned long long h3 = pack2(av.w, av.w);
            ffma2(acc_if[rr], w0.x, h0); ffma2(acc_go[rr], w0.y, h0);
            ffma2(acc_if[rr], w1.x, h1); ffma2(acc_go[rr], w1.y, h1);
            ffma2(acc_if[rr], w2.x, h2); ffma2(acc_go[rr], w2.y, h2);
            ffma2(acc_if[rr], w3.x, h3); ffma2(acc_go[rr], w3.y, h3);
        }
    }

    int u = u0 + q;
    if (u < Hn) {
        float4 bv = *(const float4*)&sB[4 * q];
        #pragma unroll
        for (int rr = 0; rr < 8; ++rr) {
            float4 o; float lo, hi;
            unpack2(acc_if[rr], lo, hi); o.x = lo + bv.x; o.y = hi + bv.y;
            unpack2(acc_go[rr], lo, hi); o.z = lo + bv.z; o.w = hi + bv.w;
            *(float4*)(g_xg + ((size_t)(rbase + r0 + rr)) * Gn + u * 4) = o;
        }
    }
}

// ---------------- persistent recurrent kernel: split-K, balanced 1 CTA/SM ----------------
// 128 CTAs = 16 unit-tiles x 8 batch-groups (32 cols). 256 threads = (q 0..15, cg 0..7, kh 0..1).
// GEMM phase: thread computes 4 cells (cols cg*4..cg*4+3) over K-half kh -> W smem traffic halved.
// Reduction phase: partials combined in smem; pointwise runs as (q, cgf 0..15) x 2 cells.
// Barrier: per-group monotone epoch counter, base-relative (no reset kernel needed).
__global__ void __launch_bounds__(256, 1)
k_rec(const float* __restrict__ Whh, int layer) {
    extern __shared__ float smem[];
    float* sW = smem;                                               // KP*64 floats        (64512 B)
    unsigned long long* sH = (unsigned long long*)(smem + KP * 64); // 32 rows * 252 u64   (64512 B)
    unsigned long long* sRed = sH + 32 * KP;                        // 2*8*4*16*2 u64      (16384 B)
    unsigned* sBase = (unsigned*)(sRed + 2048);                     // barrier base epoch

    const float* xg = g_xg;

    int tid = threadIdx.x, lane = tid & 31, w = tid >> 5;
    int ut = blockIdx.x & 15, bt = blockIdx.x >> 4;
    int u0 = ut * 16, b0 = bt * 32;
    int q = tid & 15;
    int cg = (tid >> 4) & 7;        // GEMM col-group (4 cells)
    int kh = tid >> 7;              // K-half: 0 -> kc [0,32), 1 -> kc [32,63)
    int cgf = tid >> 4;             // pointwise col-pair (2 cells), 0..15
    int c0 = cgf * 2;
    int u = u0 + q;
    bool valid = (u < Hn);

    unsigned* cnt = &g_cnt[layer][bt][0];
    unsigned* flg = &g_flag[layer][bt][0];

    fill_WT(sW, Whh, u0, Hn, KCn);
    if (tid == 0) {
        unsigned v;
        asm volatile("ld.acquire.gpu.b32 %0, [%1];" : "=r"(v) : "l"(flg) : "memory");
        *sBase = v;                 // stable: no group member can advance flag before its own arrival
    }
    __syncthreads();                // sW + sBase ready
    unsigned base = *sBase;

    int kc0 = kh ? 32 : 0;
    int kc1 = kh ? KCn : 32;

    float cv0 = 0.f, cv1 = 0.f;

    for (int t = 0; t < Tn; ++t) {
        // prefetch xg contributions for this step's pointwise cells
        float4 x0 = make_float4(0.f, 0.f, 0.f, 0.f), x1 = x0;
        if (valid) {
            size_t r0i = (size_t)t * Bn + b0 + c0;
            x0 = __ldg((const float4*)(xg + r0i * Gn + u * 4));
            x1 = __ldg((const float4*)(xg + (r0i + 1) * Gn + u * 4));
        }

        // ---- stage packed h(t) tile: warp w stages rows 4w..4w+3 ----
        {
            const unsigned long long* src = g_hd + ((size_t)t * Bn + b0 + 4 * w) * HP;
            #pragma unroll
            for (int j = 0; j < 16; ++j) {
                int i = j * 32 + lane;                 // need < 504
                if (i < 504) {
                    int row = i / 126, c2 = i - row * 126;
                    ulonglong2 v = __ldcg((const ulonglong2*)(src + (size_t)row * HP + c2 * 2));
                    *(ulonglong2*)&sH[(4 * w + row) * KP + c2 * 2] = v;
                }
            }
        }
        __syncthreads();            // cross-warp reads of sH below

        // ---- gate GEMM over this thread's K-half, 4 cells ----
        unsigned long long acc_if[4] = {0ull, 0ull, 0ull, 0ull};
        unsigned long long acc_go[4] = {0ull, 0ull, 0ull, 0ull};
        const unsigned long long* row0 = &sH[(cg * 4 + 0) * KP];
        const unsigned long long* row1 = &sH[(cg * 4 + 1) * KP];
        const unsigned long long* row2 = &sH[(cg * 4 + 2) * KP];
        const unsigned long long* row3 = &sH[(cg * 4 + 3) * KP];

        #pragma unroll 8
        for (int kc = kc0; kc < kc1; ++kc) {
            ulonglong2 w0 = *(const ulonglong2*)&sW[(kc * 4 + 0) * 64 + 4 * q];
            ulonglong2 w1 = *(const ulonglong2*)&sW[(kc * 4 + 1) * 64 + 4 * q];
            ulonglong2 w2 = *(const ulonglong2*)&sW[(kc * 4 + 2) * 64 + 4 * q];
            ulonglong2 w3 = *(const ulonglong2*)&sW[(kc * 4 + 3) * 64 + 4 * q];
#define CELL(J, ROW)                                                               \
            {                                                                      \
                ulonglong2 lo = *(const ulonglong2*)&ROW[kc * 4];                  \
                ulonglong2 hi = *(const ulonglong2*)&ROW[kc * 4 + 2];              \
                ffma2(acc_if[J], w0.x, lo.x); ffma2(acc_go[J], w0.y, lo.x);        \
                ffma2(acc_if[J], w1.x, lo.y); ffma2(acc_go[J], w1.y, lo.y);        \
                ffma2(acc_if[J], w2.x, hi.x); ffma2(acc_go[J], w2.y, hi.x);        \
                ffma2(acc_if[J], w3.x, hi.y); ffma2(acc_go[J], w3.y, hi.y);        \
            }
            CELL(0, row0) CELL(1, row1) CELL(2, row2) CELL(3, row3)
#undef CELL
        }

        // ---- write partials: sRed[kh][cg][cell][q][{if,go}] ----
        {
            unsigned long long* dst = &sRed[(((size_t)(kh * 8 + cg) * 4) * 16 + q) * 2];
            #pragma unroll
            for (int j = 0; j < 4; ++j) {
                dst[(size_t)j * 32 + 0] = acc_if[j];
                dst[(size_t)j * 32 + 1] = acc_go[j];
            }
        }
        __syncthreads();

        // ---- combine K-halves for this thread's 2 pointwise cells ----
        int rcg = cgf >> 1, rcell = (cgf & 1) * 2;
        const unsigned long long* p0 = &sRed[(((size_t)(0 * 8 + rcg) * 4 + rcell) * 16 + q) * 2];
        const unsigned long long* p1 = &sRed[(((size_t)(1 * 8 + rcg) * 4 + rcell) * 16 + q) * 2];
        unsigned long long A_if = add2(p0[0],  p1[0]);
        unsigned long long A_go = add2(p0[1],  p1[1]);
        unsigned long long B_if = add2(p0[32], p1[32]);
        unsigned long long B_go = add2(p0[33], p1[33]);

        // ---- pointwise LSTM cells + h stores ----
        {
            float gi, gf, gg, go;
            unpack2(A_if, gi, gf); unpack2(A_go, gg, go);
            float iv = sigf(gi + x0.x);
            float fv = sigf(gf + x0.y);
            float gv = tanhfast(gg + x0.z);
            float ov = sigf(go + x0.w);
            cv0 = fv * cv0 + iv * gv;
            float hv = ov * tanhfast(cv0);
            if (valid) {
                size_t wi = ((size_t)(t + 1) * Bn + b0 + c0) * HP + u;
                __stcg((unsigned long long*)(g_hd + wi), pack2(hv, hv));
                if (layer == 0) __stcg(g_h1 + wi, hv);
            }
        }
        {
            float gi, gf, gg, go;
            unpack2(B_if, gi, gf); unpack2(B_go, gg, go);
            float iv = sigf(gi + x1.x);
            float fv = sigf(gf + x1.y);
            float gv = tanhfast(gg + x1.z);
            float ov = sigf(go + x1.w);
            cv1 = fv * cv1 + iv * gv;
            float hv = ov * tanhfast(cv1);
            if (valid) {
                size_t wi = ((size_t)(t + 1) * Bn + b0 + c0 + 1) * HP + u;
                __stcg((unsigned long long*)(g_hd + wi), pack2(hv, hv));
                if (layer == 0) __stcg(g_h1 + wi, hv);
            }
        }

        // ---- 16-CTA group barrier: base-relative monotone epoch ----
        __syncthreads();
        if (tid == 0) {
            __threadfence();                          // cumulative release of CTA's stores
            unsigned old = atomicAdd(cnt, 1u);
            unsigned epoch = base + (unsigned)(t + 1);
            if ((old & 15u) == 15u) {
                asm volatile("st.release.gpu.b32 [%0], %1;" :: "l"(flg), "r"(epoch) : "memory");
            }
            unsigned v;
            do {
                asm volatile("ld.acquire.gpu.b32 %0, [%1];" : "=r"(v) : "l"(flg) : "memory");
            } while (v < epoch);
        }
        __syncthreads();
    }
}

// ---------------- output head (reads packed h2) ----------------
__global__ void __launch_bounds__(256, 1)
k_head(const float* __restrict__ Wl, const float* __restrict__ bl, float* __restrict__ out) {
    __shared__ float sw[256];
    int tid = threadIdx.x;
    sw[tid] = (tid < Hn) ? Wl[tid] : 0.f;
    __syncthreads();
    int warp = tid >> 5, lane = tid & 31;
    int r = blockIdx.x * 8 + warp;          // r = b*T + t (output order)
    int t = r & (Tn - 1);
    int b = r >> 9;
    const unsigned long long* hrow = g_hd + ((size_t)(t + 1) * Bn + b) * HP;
    float p = 0.f;
    #pragma unroll
    for (int j = 0; j < 8; ++j) {
        int k = j * 32 + lane;
        float lo, hi;
        unpack2(__ldg(hrow + k), lo, hi);
        p = fmaf(sw[k], lo, p);
    }
    #pragma unroll
    for (int off = 16; off; off >>= 1) p += __shfl_xor_sync(0xffffffffu, p, off);
    if (lane == 0) out[r] = 1.f / (1.f + __expf(-(p + bl[0])));
}

// ---------------- launcher ----------------
extern "C" void kernel_launch(void* const* d_in, const int* in_sizes, int n_in,
                              void* d_out, int out_size) {
    const float* x    = (const float*)d_in[0];
    const float* Wih0 = (const float*)d_in[1];
    const float* Whh0 = (const float*)d_in[2];
    const float* bih0 = (const float*)d_in[3];
    const float* bhh0 = (const float*)d_in[4];
    const float* Wih1 = (const float*)d_in[5];
    const float* Whh1 = (const float*)d_in[6];
    const float* bih1 = (const float*)d_in[7];
    const float* bhh1 = (const float*)d_in[8];
    const float* Wlin = (const float*)d_in[9];
    const float* blin = (const float*)d_in[10];
    float* out = (float*)d_out;

    const int smem_rec   = (KP * 64) * 4 + 32 * KP * 8 + 2048 * 8 + 16;  // 145,424 B
    const int smem_gemm1 = (KCn * 4 * 64 + 128 * 260 + 64) * 4;          // 197,888 B
    const int smem_gemm0 = (10 * 4 * 64 + 128 * 48 + 64) * 4;            // 35,072 B

    cudaFuncSetAttribute(k_rec,   cudaFuncAttributeMaxDynamicSharedMemorySize, smem_rec);
    cudaFuncSetAttribute(k_xgemm, cudaFuncAttributeMaxDynamicSharedMemorySize, smem_gemm1);

    // layer 0
    k_xgemm<<<dim3(16, 1024), 256, smem_gemm0>>>(x, Wih0, bih0, bhh0, 0, 40, 10, 48);
    k_rec<<<128, 256, smem_rec>>>(Whh0, 0);

    // layer 1
    k_xgemm<<<dim3(16, 1024), 256, smem_gemm1>>>(nullptr, Wih1, bih1, bhh1, 1, Hn, KCn, 260);
    k_rec<<<128, 256, smem_rec>>>(Whh1, 1);

    // head
    k_head<<<16384, 256>>>(Wlin, blin, out);
}

// round 15
// speedup vs baseline: 2.5662x; 1.1009x over previous
#include <cuda_runtime.h>
#include <cuda_bf16.h>
#include <cstdint>

#define Hn    250       // hidden units
#define Bn    256       // batch
#define Tn    512       // time steps
#define Gn    1000      // 4*H gate rows
#define HP    256       // padded hidden stride (u64 pairs)
#define KP    252       // padded K for recurrent GEMM
#define KCn   63        // KP/4 chunks

// ---------------- scratch (device globals; zero-initialized at load) ----------------
__device__ float              g_xg[(size_t)Tn * Bn * Gn];          // input-gate contributions (layer 0, then overwritten per-t for layer 1)
__device__ unsigned long long g_hd[(size_t)(Tn + 1) * Bn * HP];    // duplicated {h,h} pairs (both layers reuse; slice 0 zeros)
__device__ unsigned           g_cnt [2][8][32];                    // per-(layer, batch-group) monotone arrive counters
__device__ unsigned           g_flag[2][8][32];                    // per-(layer, batch-group) monotone epoch flags

// ---------------- helpers ----------------
__device__ __forceinline__ float sigf(float x) { return 1.f / (1.f + __expf(-x)); }
__device__ __forceinline__ float tanhfast(float x) { return 1.f - 2.f / (__expf(2.f * x) + 1.f); }

__device__ __forceinline__ unsigned long long pack2(float lo, float hi) {
    unsigned long long r;
    asm("mov.b64 %0, {%1, %2};" : "=l"(r) : "f"(lo), "f"(hi));
    return r;
}
__device__ __forceinline__ void unpack2(unsigned long long v, float& lo, float& hi) {
    asm("mov.b64 {%0, %1}, %2;" : "=f"(lo), "=f"(hi) : "l"(v));
}
__device__ __forceinline__ void ffma2(unsigned long long& acc, unsigned long long a, unsigned long long b) {
    asm("fma.rn.f32x2 %0, %1, %2, %0;" : "+l"(acc) : "l"(a), "l"(b));
}
__device__ __forceinline__ unsigned long long add2(unsigned long long a, unsigned long long b) {
    unsigned long long r;
    asm("add.rn.f32x2 %0, %1, %2;" : "=l"(r) : "l"(a), "l"(b));
    return r;
}

// Transposed, gate-interleaved weight tile: sW[k*64 + m], m = u_local*4 + g.
__device__ void fill_WT(float* sW, const float* __restrict__ W, int u0, int Kreal, int kc_n) {
    int total = 64 * kc_n;
    for (int i = threadIdx.x; i < total; i += blockDim.x) {
        int m  = i / kc_n;
        int kc = i - m * kc_n;
        int k  = kc * 4;
        int g  = m & 3;
        int u  = u0 + (m >> 2);
        float4 v = make_float4(0.f, 0.f, 0.f, 0.f);
        if (u < Hn) {
            const float* src = W + (size_t)(g * Hn + u) * Kreal + k;
            if (k + 0 < Kreal) v.x = src[0];
            if (k + 1 < Kreal) v.y = src[1];
            if (k + 2 < Kreal) v.z = src[2];
            if (k + 3 < Kreal) v.w = src[3];
        }
        sW[(k + 0) * 64 + m] = v.x;
        sW[(k + 1) * 64 + m] = v.y;
        sW[(k + 2) * 64 + m] = v.z;
        sW[(k + 3) * 64 + m] = v.w;
    }
}

// ---------------- layer-0 input GEMM (K=40): 128 rows x 64 cols, 8-row register blocking ----------------
__global__ void __launch_bounds__(256, 1)
k_xgemm0(const float* __restrict__ A_in, const float* __restrict__ Wih,
         const float* __restrict__ bih, const float* __restrict__ bhh) {
    const int kc_n = 10, astride = 48;
    extern __shared__ float smem[];
    float* sW = smem;                          // 40 * 64
    float* sA = sW + kc_n * 4 * 64;            // 128 * 48
    float* sB = sA + 128 * astride;            // 64 bias
    int tid = threadIdx.x;
    int u0 = blockIdx.x * 16;
    int rbase = blockIdx.y * 128;

    fill_WT(sW, Wih, u0, 40, kc_n);
    if (tid < 64) {
        int g = tid & 3, u = u0 + (tid >> 2);
        sB[tid] = (u < Hn) ? (bih[g * Hn + u] + bhh[g * Hn + u]) : 0.f;
    }
    for (int i = tid; i < 128 * 10; i += 256) {
        int row = i / 10, c4 = i - row * 10;
        int r = rbase + row;
        int tt = r >> 8, b = r & 255;
        *(float4*)&sA[row * astride + c4 * 4] =
            __ldg((const float4*)(A_in + ((size_t)b * Tn + tt) * 40 + c4 * 4));
    }
    __syncthreads();

    int q = tid & 15, rg = tid >> 4;
    int r0 = rg * 8;
    unsigned long long acc_if[8], acc_go[8];
    #pragma unroll
    for (int rr = 0; rr < 8; ++rr) { acc_if[rr] = 0ull; acc_go[rr] = 0ull; }

    #pragma unroll
    for (int kc = 0; kc < kc_n; ++kc) {
        int k = kc * 4;
        ulonglong2 w0 = *(const ulonglong2*)&sW[(k + 0) * 64 + 4 * q];
        ulonglong2 w1 = *(const ulonglong2*)&sW[(k + 1) * 64 + 4 * q];
        ulonglong2 w2 = *(const ulonglong2*)&sW[(k + 2) * 64 + 4 * q];
        ulonglong2 w3 = *(const ulonglong2*)&sW[(k + 3) * 64 + 4 * q];
        #pragma unroll
        for (int rr = 0; rr < 8; ++rr) {
            float4 av = *(const float4*)&sA[(r0 + rr) * astride + k];
            unsigned long long h0 = pack2(av.x, av.x);
            unsigned long long h1 = pack2(av.y, av.y);
            unsigned long long h2 = pack2(av.z, av.z);
            unsigned long long h3 = pack2(av.w, av.w);
            ffma2(acc_if[rr], w0.x, h0); ffma2(acc_go[rr], w0.y, h0);
            ffma2(acc_if[rr], w1.x, h1); ffma2(acc_go[rr], w1.y, h1);
            ffma2(acc_if[rr], w2.x, h2); ffma2(acc_go[rr], w2.y, h2);
            ffma2(acc_if[rr], w3.x, h3); ffma2(acc_go[rr], w3.y, h3);
        }
    }

    int u = u0 + q;
    if (u < Hn) {
        float4 bv = *(const float4*)&sB[4 * q];
        #pragma unroll
        for (int rr = 0; rr < 8; ++rr) {
            float4 o; float lo, hi;
            unpack2(acc_if[rr], lo, hi); o.x = lo + bv.x; o.y = hi + bv.y;
            unpack2(acc_go[rr], lo, hi); o.z = lo + bv.z; o.w = hi + bv.w;
            *(float4*)(g_xg + ((size_t)(rbase + r0 + rr)) * Gn + u * 4) = o;
        }
    }
}

// ---------------- persistent recurrent kernel (optionally fused with next-layer input GEMM) ----------------
// 128 CTAs = 16 unit-tiles x 8 batch-groups (32 cols). 256 threads = (q 0..15, cg 0..7, kh 0..1).
// FUSED=1 (layer 0): per step also computes xg1[t-1] = W_ih1 @ h0(t-1) + b from the SAME staged tile,
// reusing sRed in a second reduction round; epilogue iteration produces xg1[Tn-1].
template<int FUSED>
__global__ void __launch_bounds__(256, 1)
k_rec(const float* __restrict__ Whh, const float* __restrict__ Wih2,
      const float* __restrict__ bih2, const float* __restrict__ bhh2, int layer) {
    extern __shared__ float smem[];
    float* sW1 = smem;                                               // KP*64 f32     (64512 B)
    unsigned long long* sH = (unsigned long long*)(smem + KP * 64);  // 32*252 u64    (64512 B)
    unsigned long long* sRed = sH + 32 * KP;                         // 2048 u64      (16384 B)
    unsigned* sBase = (unsigned*)(sRed + 2048);                      // 16 B
    float* sW2 = (float*)((char*)smem + 145424);                     // KP*64 f32 (FUSED only)

    const float* xg = g_xg;

    int tid = threadIdx.x, lane = tid & 31, w = tid >> 5;
    int ut = blockIdx.x & 15, bt = blockIdx.x >> 4;
    int u0 = ut * 16, b0 = bt * 32;
    int q = tid & 15;
    int cg = (tid >> 4) & 7;        // GEMM col-group (4 cells)
    int kh = tid >> 7;              // K-half
    int cgf = tid >> 4;             // pointwise col-pair, 0..15
    int c0 = cgf * 2;
    int u = u0 + q;
    bool valid = (u < Hn);

    unsigned* cnt = &g_cnt[layer][bt][0];
    unsigned* flg = &g_flag[layer][bt][0];

    fill_WT(sW1, Whh, u0, Hn, KCn);
    if (FUSED) fill_WT(sW2, Wih2, u0, Hn, KCn);

    unsigned long long b2_if = 0ull, b2_go = 0ull;
    if (FUSED && valid) {
        b2_if = pack2(bih2[0 * Hn + u] + bhh2[0 * Hn + u], bih2[1 * Hn + u] + bhh2[1 * Hn + u]);
        b2_go = pack2(bih2[2 * Hn + u] + bhh2[2 * Hn + u], bih2[3 * Hn + u] + bhh2[3 * Hn + u]);
    }

    if (tid == 0) {
        unsigned v;
        asm volatile("ld.acquire.gpu.b32 %0, [%1];" : "=r"(v) : "l"(flg) : "memory");
        *sBase = v;
    }
    __syncthreads();
    unsigned base = *sBase;

    int kc0 = kh ? 32 : 0;
    int kc1 = kh ? KCn : 32;
    int rcg = cgf >> 1, rcell = (cgf & 1) * 2;
    unsigned long long* redDst = &sRed[(((size_t)(kh * 8 + cg) * 4) * 16 + q) * 2];
    const unsigned long long* p0 = &sRed[(((size_t)(0 * 8 + rcg) * 4 + rcell) * 16 + q) * 2];
    const unsigned long long* p1 = &sRed[(((size_t)(1 * 8 + rcg) * 4 + rcell) * 16 + q) * 2];

    float cv0 = 0.f, cv1 = 0.f;

    for (int t = 0; t < Tn; ++t) {
        // prefetch xg for this step's pointwise cells
        float4 x0 = make_float4(0.f, 0.f, 0.f, 0.f), x1 = x0;
        if (valid) {
            size_t r0i = (size_t)t * Bn + b0 + c0;
            x0 = __ldg((const float4*)(xg + r0i * Gn + u * 4));
            x1 = __ldg((const float4*)(xg + (r0i + 1) * Gn + u * 4));
        }

        // ---- stage packed h(t) tile: warp w stages rows 4w..4w+3 ----
        {
            const unsigned long long* src = g_hd + ((size_t)t * Bn + b0 + 4 * w) * HP;
            #pragma unroll
            for (int j = 0; j < 16; ++j) {
                int i = j * 32 + lane;
                if (i < 504) {
                    int row = i / 126, c2 = i - row * 126;
                    ulonglong2 v = __ldcg((const ulonglong2*)(src + (size_t)row * HP + c2 * 2));
                    *(ulonglong2*)&sH[(4 * w + row) * KP + c2 * 2] = v;
                }
            }
        }
        __syncthreads();

        // ---- dual gate GEMM over this thread's K-half, 4 cells ----
        unsigned long long aR_if[4] = {0ull,0ull,0ull,0ull}, aR_go[4] = {0ull,0ull,0ull,0ull};
        unsigned long long aX_if[4] = {0ull,0ull,0ull,0ull}, aX_go[4] = {0ull,0ull,0ull,0ull};
        const unsigned long long* row0 = &sH[(cg * 4 + 0) * KP];
        const unsigned long long* row1 = &sH[(cg * 4 + 1) * KP];
        const unsigned long long* row2 = &sH[(cg * 4 + 2) * KP];
        const unsigned long long* row3 = &sH[(cg * 4 + 3) * KP];

        #pragma unroll 2
        for (int kc = kc0; kc < kc1; ++kc) {
            ulonglong2 w0 = *(const ulonglong2*)&sW1[(kc * 4 + 0) * 64 + 4 * q];
            ulonglong2 w1 = *(const ulonglong2*)&sW1[(kc * 4 + 1) * 64 + 4 * q];
            ulonglong2 w2 = *(const ulonglong2*)&sW1[(kc * 4 + 2) * 64 + 4 * q];
            ulonglong2 w3 = *(const ulonglong2*)&sW1[(kc * 4 + 3) * 64 + 4 * q];
            ulonglong2 v0, v1, v2, v3;
            if (FUSED) {
                v0 = *(const ulonglong2*)&sW2[(kc * 4 + 0) * 64 + 4 * q];
                v1 = *(const ulonglong2*)&sW2[(kc * 4 + 1) * 64 + 4 * q];
                v2 = *(const ulonglong2*)&sW2[(kc * 4 + 2) * 64 + 4 * q];
                v3 = *(const ulonglong2*)&sW2[(kc * 4 + 3) * 64 + 4 * q];
            }
#define CELL(J, ROW)                                                                \
            {                                                                       \
                ulonglong2 lo = *(const ulonglong2*)&ROW[kc * 4];                   \
                ulonglong2 hi = *(const ulonglong2*)&ROW[kc * 4 + 2];               \
                ffma2(aR_if[J], w0.x, lo.x); ffma2(aR_go[J], w0.y, lo.x);           \
                ffma2(aR_if[J], w1.x, lo.y); ffma2(aR_go[J], w1.y, lo.y);           \
                ffma2(aR_if[J], w2.x, hi.x); ffma2(aR_go[J], w2.y, hi.x);           \
                ffma2(aR_if[J], w3.x, hi.y); ffma2(aR_go[J], w3.y, hi.y);           \
                if (FUSED) {                                                        \
                    ffma2(aX_if[J], v0.x, lo.x); ffma2(aX_go[J], v0.y, lo.x);       \
                    ffma2(aX_if[J], v1.x, lo.y); ffma2(aX_go[J], v1.y, lo.y);       \
                    ffma2(aX_if[J], v2.x, hi.x); ffma2(aX_go[J], v2.y, hi.x);       \
                    ffma2(aX_if[J], v3.x, hi.y); ffma2(aX_go[J], v3.y, hi.y);       \
                }                                                                   \
            }
            CELL(0, row0) CELL(1, row1) CELL(2, row2) CELL(3, row3)
#undef CELL
        }

        // ---- reduction round 1: recurrent partials ----
        #pragma unroll
        for (int j = 0; j < 4; ++j) {
            redDst[(size_t)j * 32 + 0] = aR_if[j];
            redDst[(size_t)j * 32 + 1] = aR_go[j];
        }
        __syncthreads();

        unsigned long long A_if = add2(p0[0],  p1[0]);
        unsigned long long A_go = add2(p0[1],  p1[1]);
        unsigned long long B_if = add2(p0[32], p1[32]);
        unsigned long long B_go = add2(p0[33], p1[33]);

        // ---- pointwise LSTM cells + h stores ----
        {
            float gi, gf, gg, go;
            unpack2(A_if, gi, gf); unpack2(A_go, gg, go);
            float iv = sigf(gi + x0.x);
            float fv = sigf(gf + x0.y);
            float gv = tanhfast(gg + x0.z);
            float ov = sigf(go + x0.w);
            cv0 = fv * cv0 + iv * gv;
            float hv = ov * tanhfast(cv0);
            if (valid) {
                size_t wi = ((size_t)(t + 1) * Bn + b0 + c0) * HP + u;
                __stcg((unsigned long long*)(g_hd + wi), pack2(hv, hv));
            }
        }
        {
            float gi, gf, gg, go;
            unpack2(B_if, gi, gf); unpack2(B_go, gg, go);
            float iv = sigf(gi + x1.x);
            float fv = sigf(gf + x1.y);
            float gv = tanhfast(gg + x1.z);
            float ov = sigf(go + x1.w);
            cv1 = fv * cv1 + iv * gv;
            float hv = ov * tanhfast(cv1);
            if (valid) {
                size_t wi = ((size_t)(t + 1) * Bn + b0 + c0 + 1) * HP + u;
                __stcg((unsigned long long*)(g_hd + wi), pack2(hv, hv));
            }
        }

        // ---- reduction round 2 (FUSED): xg1[t-1] partials -> combine -> store ----
        if (FUSED) {
            __syncthreads();            // all round-1 reads of sRed complete
            #pragma unroll
            for (int j = 0; j < 4; ++j) {
                redDst[(size_t)j * 32 + 0] = aX_if[j];
                redDst[(size_t)j * 32 + 1] = aX_go[j];
            }
            __syncthreads();
            if (valid && t >= 1) {
                ulonglong2 o0, o1;
                o0.x = add2(add2(p0[0],  p1[0]),  b2_if);
                o0.y = add2(add2(p0[1],  p1[1]),  b2_go);
                o1.x = add2(add2(p0[32], p1[32]), b2_if);
                o1.y = add2(add2(p0[33], p1[33]), b2_go);
                size_t row = (size_t)(t - 1) * Bn + b0 + c0;
                *(ulonglong2*)(g_xg + row * Gn + u * 4) = o0;
                *(ulonglong2*)(g_xg + (row + 1) * Gn + u * 4) = o1;
            }
        }

        // ---- 16-CTA group barrier: base-relative monotone epoch ----
        __syncthreads();
        if (tid == 0) {
            __threadfence();
            unsigned old = atomicAdd(cnt, 1u);
            unsigned epoch = base + (unsigned)(t + 1);
            if ((old & 15u) == 15u) {
                asm volatile("st.release.gpu.b32 [%0], %1;" :: "l"(flg), "r"(epoch) : "memory");
            }
            unsigned v;
            do {
                asm volatile("ld.acquire.gpu.b32 %0, [%1];" : "=r"(v) : "l"(flg) : "memory");
            } while (v < epoch);
        }
        __syncthreads();
    }

    // ---- FUSED epilogue: xg1[Tn-1] from h0(Tn-1) = slot Tn ----
    if (FUSED) {
        {
            const unsigned long long* src = g_hd + ((size_t)Tn * Bn + b0 + 4 * w) * HP;
            #pragma unroll
            for (int j = 0; j < 16; ++j) {
                int i = j * 32 + lane;
                if (i < 504) {
                    int row = i / 126, c2 = i - row * 126;
                    ulonglong2 v = __ldcg((const ulonglong2*)(src + (size_t)row * HP + c2 * 2));
                    *(ulonglong2*)&sH[(4 * w + row) * KP + c2 * 2] = v;
                }
            }
        }
        __syncthreads();

        unsigned long long aX_if[4] = {0ull,0ull,0ull,0ull}, aX_go[4] = {0ull,0ull,0ull,0ull};
        const unsigned long long* row0 = &sH[(cg * 4 + 0) * KP];
        const unsigned long long* row1 = &sH[(cg * 4 + 1) * KP];
        const unsigned long long* row2 = &sH[(cg * 4 + 2) * KP];
        const unsigned long long* row3 = &sH[(cg * 4 + 3) * KP];
        #pragma unroll 4
        for (int kc = kc0; kc < kc1; ++kc) {
            ulonglong2 v0 = *(const ulonglong2*)&sW2[(kc * 4 + 0) * 64 + 4 * q];
            ulonglong2 v1 = *(const ulonglong2*)&sW2[(kc * 4 + 1) * 64 + 4 * q];
            ulonglong2 v2 = *(const ulonglong2*)&sW2[(kc * 4 + 2) * 64 + 4 * q];
            ulonglong2 v3 = *(const ulonglong2*)&sW2[(kc * 4 + 3) * 64 + 4 * q];
#define CELLX(J, ROW)                                                               \
            {                                                                       \
                ulonglong2 lo = *(const ulonglong2*)&ROW[kc * 4];                   \
                ulonglong2 hi = *(const ulonglong2*)&ROW[kc * 4 + 2];               \
                ffma2(aX_if[J], v0.x, lo.x); ffma2(aX_go[J], v0.y, lo.x);           \
                ffma2(aX_if[J], v1.x, lo.y); ffma2(aX_go[J], v1.y, lo.y);           \
                ffma2(aX_if[J], v2.x, hi.x); ffma2(aX_go[J], v2.y, hi.x);           \
                ffma2(aX_if[J], v3.x, hi.y); ffma2(aX_go[J], v3.y, hi.y);           \
            }
            CELLX(0, row0) CELLX(1, row1) CELLX(2, row2) CELLX(3, row3)
#undef CELLX
        }
        #pragma unroll
        for (int j = 0; j < 4; ++j) {
            redDst[(size_t)j * 32 + 0] = aX_if[j];
            redDst[(size_t)j * 32 + 1] = aX_go[j];
        }
        __syncthreads();
        if (valid) {
            ulonglong2 o0, o1;
            o0.x = add2(add2(p0[0],  p1[0]),  b2_if);
            o0.y = add2(add2(p0[1],  p1[1]),  b2_go);
            o1.x = add2(add2(p0[32], p1[32]), b2_if);
            o1.y = add2(add2(p0[33], p1[33]), b2_go);
            size_t row = (size_t)(Tn - 1) * Bn + b0 + c0;
            *(ulonglong2*)(g_xg + row * Gn + u * 4) = o0;
            *(ulonglong2*)(g_xg + (row + 1) * Gn + u * 4) = o1;
        }
    }
}

// ---------------- output head (reads packed h2) ----------------
__global__ void __launch_bounds__(256, 1)
k_head(const float* __restrict__ Wl, const float* __restrict__ bl, float* __restrict__ out) {
    __shared__ float sw[256];
    int tid = threadIdx.x;
    sw[tid] = (tid < Hn) ? Wl[tid] : 0.f;
    __syncthreads();
    int warp = tid >> 5, lane = tid & 31;
    int r = blockIdx.x * 8 + warp;          // r = b*T + t (output order)
    int t = r & (Tn - 1);
    int b = r >> 9;
    const unsigned long long* hrow = g_hd + ((size_t)(t + 1) * Bn + b) * HP;
    float p = 0.f;
    #pragma unroll
    for (int j = 0; j < 8; ++j) {
        int k = j * 32 + lane;
        float lo, hi;
        unpack2(__ldg(hrow + k), lo, hi);
        p = fmaf(sw[k], lo, p);
    }
    #pragma unroll
    for (int off = 16; off; off >>= 1) p += __shfl_xor_sync(0xffffffffu, p, off);
    if (lane == 0) out[r] = 1.f / (1.f + __expf(-(p + bl[0])));
}

// ---------------- launcher ----------------
extern "C" void kernel_launch(void* const* d_in, const int* in_sizes, int n_in,
                              void* d_out, int out_size) {
    const float* x    = (const float*)d_in[0];
    const float* Wih0 = (const float*)d_in[1];
    const float* Whh0 = (const float*)d_in[2];
    const float* bih0 = (const float*)d_in[3];
    const float* bhh0 = (const float*)d_in[4];
    const float* Wih1 = (const float*)d_in[5];
    const float* Whh1 = (const float*)d_in[6];
    const float* bih1 = (const float*)d_in[7];
    const float* bhh1 = (const float*)d_in[8];
    const float* Wlin = (const float*)d_in[9];
    const float* blin = (const float*)d_in[10];
    float* out = (float*)d_out;

    const int smem_rec1  = 145424 + KP * 64 * 4;   // 209,936 B (fused: + W_ih1 tile)
    const int smem_rec0  = 145424;                 // 145,424 B
    const int smem_gemm0 = (10 * 4 * 64 + 128 * 48 + 64) * 4;   // 35,072 B

    cudaFuncSetAttribute(k_rec<1>, cudaFuncAttributeMaxDynamicSharedMemorySize, smem_rec1);
    cudaFuncSetAttribute(k_rec<0>, cudaFuncAttributeMaxDynamicSharedMemorySize, smem_rec0);

    // layer-0 input contributions
    k_xgemm0<<<dim3(16, 1024), 256, smem_gemm0>>>(x, Wih0, bih0, bhh0);
    // layer-0 recurrence, fused with layer-1 input GEMM
    k_rec<1><<<128, 256, smem_rec1>>>(Whh0, Wih1, bih1, bhh1, 0);
    // layer-1 recurrence
    k_rec<0><<<128, 256, smem_rec0>>>(Whh1, nullptr, nullptr, nullptr, 1);
    // head
    k_head<<<16384, 256>>>(Wlin, blin, out);
}